// round 16
// baseline (speedup 1.0000x reference)
#include <cuda_runtime.h>
#include <cuda_bf16.h>
#include <cstdint>

#define N_PTS 8192
#define E_DIM 256
#define NUM_CLASSES 100
#define MARGIN 0.1f
#define EPS_F 1e-4f

#define BT 128                        // tile edge (rows and cols)
#define SAB8 272                      // padded row stride in bytes
#define NRB (N_PTS / BT)              // 64 row blocks
#define NTILES (NRB * (NRB + 1) / 2)  // 2080 triangular tiles
#define NTHREADS 1024

__device__ float g_sq[N_PTS];
__device__ int   g_hist[NUM_CLASSES];
__device__ float g_num[N_PTS];
__device__ float g_den[N_PTS];
__device__ unsigned g_done;
__device__ uint8_t g_x8[(size_t)N_PTS * E_DIM];   // e4m3 copy of X (2MB)

__device__ __forceinline__ void mma_fp8(float acc[4], const uint32_t a[4],
                                        const uint32_t b[2]) {
    asm volatile(
        "mma.sync.aligned.m16n8k32.row.col.f32.e4m3.e4m3.f32 "
        "{%0,%1,%2,%3}, {%4,%5,%6,%7}, {%8,%9}, {%0,%1,%2,%3};"
        : "+f"(acc[0]), "+f"(acc[1]), "+f"(acc[2]), "+f"(acc[3])
        : "r"(a[0]), "r"(a[1]), "r"(a[2]), "r"(a[3]), "r"(b[0]), "r"(b[1]));
}

__device__ __forceinline__ uint16_t pack_e4m3x2(float lo, float hi) {
    uint16_t h;
    asm("cvt.rn.satfinite.e4m3x2.f32 %0, %1, %2;" : "=h"(h) : "f"(hi), "f"(lo));
    return h;
}

// ---------------------------------------------------------------------------
// Per-row squared norms (fp32 exact) + label histogram + e4m3 conversion.
// ---------------------------------------------------------------------------
__global__ void prep_kernel(const float* __restrict__ X, const int* __restrict__ lab) {
    int warp = (blockIdx.x * blockDim.x + threadIdx.x) >> 5;
    int lane = threadIdx.x & 31;
    if (warp >= N_PTS) return;
    const float4* row = (const float4*)(X + (size_t)warp * E_DIM);
    float4 v0 = row[2 * lane];
    float4 v1 = row[2 * lane + 1];
    float s = v0.x * v0.x + v0.y * v0.y + v0.z * v0.z + v0.w * v0.w
            + v1.x * v1.x + v1.y * v1.y + v1.z * v1.z + v1.w * v1.w;

    uint32_t w0 = (uint32_t)pack_e4m3x2(v0.x, v0.y)
                | ((uint32_t)pack_e4m3x2(v0.z, v0.w) << 16);
    uint32_t w1 = (uint32_t)pack_e4m3x2(v1.x, v1.y)
                | ((uint32_t)pack_e4m3x2(v1.z, v1.w) << 16);
    uint2 u; u.x = w0; u.y = w1;
    ((uint2*)(g_x8 + (size_t)warp * E_DIM))[lane] = u;

#pragma unroll
    for (int o = 16; o; o >>= 1) s += __shfl_xor_sync(0xffffffffu, s, o);
    if (lane == 0) {
        g_sq[warp] = s;
        atomicAdd(&g_hist[lab[warp]], 1);
    }
}

// ---------------------------------------------------------------------------
// Symmetric-Gram e4m3 m16n8k32 kernel. One CTA per triangular tile (I,J), J<=I.
// 1024 threads = 32 warps (8/SMSP), warp grid 4(m) x 8(n), warp tile 32x16.
// Off-diagonal tiles scatter BOTH row-side (I) and column-side (J) partials.
// Last CTA performs the final reduction AND resets state for the next replay.
// ---------------------------------------------------------------------------
__global__ void __launch_bounds__(NTHREADS, 1)
triplet_main_kernel(const int* __restrict__ lab, float* __restrict__ out) {
    extern __shared__ uint8_t smb[];
    uint8_t* As8 = smb;                  // BT x SAB8 (rows of I)
    uint8_t* Bs8 = smb + BT * SAB8;      // BT x SAB8 (rows of J = columns)

    __shared__ float sqb_s[BT];
    __shared__ int   lbb_s[BT];
    __shared__ float red_n[BT][8];
    __shared__ float red_d[BT][8];
    __shared__ float colp_n[4][BT];
    __shared__ float colp_d[4][BT];
    __shared__ unsigned last_s;
    __shared__ double s1[NTHREADS];
    __shared__ double s2[NTHREADS];

    const int tid  = threadIdx.x;
    const int w    = tid >> 5, lane = tid & 31;
    const int wm   = w >> 3,   wn   = w & 7;       // 4x8 warp grid
    const int g    = lane >> 2, cc  = lane & 3;

    // Triangular decode: blockIdx.x -> (I, J), J <= I.
    int b = blockIdx.x;
    int I = (int)((sqrtf(8.f * (float)b + 1.f) - 1.f) * 0.5f);
    while ((I + 1) * (I + 2) / 2 <= b) ++I;
    while (I * (I + 1) / 2 > b) --I;
    const int J = b - I * (I + 1) / 2;
    const bool offdiag = (I != J);

    const int row0 = I * BT;
    const int col0 = J * BT;
    const float DIAG_D = sqrtf(EPS_F);

    // Load A (I rows) and B (J rows): 2048 uint4 each, 2 per thread each.
#pragma unroll
    for (int q = 0; q < 2; ++q) {
        int idx = tid + q * NTHREADS;
        int r = idx >> 4, c16 = idx & 15;
        uint4 u = ((const uint4*)(g_x8 + (size_t)(row0 + r) * E_DIM))[c16];
        *(uint4*)(As8 + (size_t)r * SAB8 + c16 * 16) = u;
    }
#pragma unroll
    for (int q = 0; q < 2; ++q) {
        int idx = tid + q * NTHREADS;
        int r = idx >> 4, c16 = idx & 15;
        uint4 u = ((const uint4*)(g_x8 + (size_t)(col0 + r) * E_DIM))[c16];
        *(uint4*)(Bs8 + (size_t)r * SAB8 + c16 * 16) = u;
    }
    if (tid < BT) {
        sqb_s[tid] = g_sq[col0 + tid];
        lbb_s[tid] = lab[col0 + tid];
    }

    float sqa[4]; int la[4];
#pragma unroll
    for (int mf = 0; mf < 2; ++mf)
#pragma unroll
        for (int hi = 0; hi < 2; ++hi) {
            int r = row0 + wm * 32 + mf * 16 + g + hi * 8;
            sqa[mf * 2 + hi] = g_sq[r];
            la[mf * 2 + hi]  = lab[r];
        }
    __syncthreads();

    float acc[2][2][4];
#pragma unroll
    for (int mf = 0; mf < 2; ++mf)
#pragma unroll
        for (int nf = 0; nf < 2; ++nf)
#pragma unroll
            for (int e = 0; e < 4; ++e) acc[mf][nf][e] = 0.f;

#pragma unroll
    for (int ks = 0; ks < E_DIM / 32; ++ks) {
        const int kc = ks * 32;
        uint32_t a[2][4], bb[2][2];
#pragma unroll
        for (int mf = 0; mf < 2; ++mf) {
            int r = wm * 32 + mf * 16 + g;
            a[mf][0] = *(const uint32_t*)(As8 + (size_t)r * SAB8 + kc + 4 * cc);
            a[mf][1] = *(const uint32_t*)(As8 + (size_t)(r + 8) * SAB8 + kc + 4 * cc);
            a[mf][2] = *(const uint32_t*)(As8 + (size_t)r * SAB8 + kc + 4 * cc + 16);
            a[mf][3] = *(const uint32_t*)(As8 + (size_t)(r + 8) * SAB8 + kc + 4 * cc + 16);
        }
#pragma unroll
        for (int nf = 0; nf < 2; ++nf) {
            int n = wn * 16 + nf * 8 + g;
            bb[nf][0] = *(const uint32_t*)(Bs8 + (size_t)n * SAB8 + kc + 4 * cc);
            bb[nf][1] = *(const uint32_t*)(Bs8 + (size_t)n * SAB8 + kc + 4 * cc + 16);
        }
#pragma unroll
        for (int mf = 0; mf < 2; ++mf)
#pragma unroll
            for (int nf = 0; nf < 2; ++nf)
                mma_fp8(acc[mf][nf], a[mf], bb[nf]);
    }

    // Epilogue: one rsqrt per element; value feeds row (I) and column (J) sums.
    float num[4] = {0.f, 0.f, 0.f, 0.f};
    float den[4] = {0.f, 0.f, 0.f, 0.f};
    float cn[4]  = {0.f, 0.f, 0.f, 0.f};
    float cd[4]  = {0.f, 0.f, 0.f, 0.f};

    float sj[2][2]; int lj[2][2];
#pragma unroll
    for (int nf = 0; nf < 2; ++nf)
#pragma unroll
        for (int e0 = 0; e0 < 2; ++e0) {
            int jl = wn * 16 + nf * 8 + 2 * cc + e0;
            sj[nf][e0] = sqb_s[jl];
            lj[nf][e0] = lbb_s[jl];
        }

#pragma unroll
    for (int mf = 0; mf < 2; ++mf)
#pragma unroll
        for (int nf = 0; nf < 2; ++nf)
#pragma unroll
            for (int e = 0; e < 4; ++e) {
                int hi = e >> 1, e0 = e & 1;
                int id = mf * 2 + hi;
                int ci = nf * 2 + e0;
                float v = fmaxf(sqa[id] + sj[nf][e0] - 2.f * acc[mf][nf][e], EPS_F);
                float r;
                asm("rsqrt.approx.f32 %0, %1;" : "=f"(r) : "f"(v));
                if (la[id] == lj[nf][e0]) {
                    float c;
                    if (offdiag) {
                        c = v * r;
                    } else {
                        int il = wm * 32 + mf * 16 + g + hi * 8;
                        int jl = wn * 16 + nf * 8 + 2 * cc + e0;
                        c = (il == jl) ? DIAG_D : v * r;
                    }
                    num[id] += c;
                    cn[ci]  += c;
                } else {
                    float t = MARGIN * r;
                    float u = 1.f - t;
                    float c = r * fmaf(t * t, u, u);   // 1/(d+m) ~ r(1-t)(1+t^2)
                    den[id] += c;
                    cd[ci]  += c;
                }
            }

    // ---- Row-side reduce (over cc: xor 1,2 stays within quad) ----
#pragma unroll
    for (int id = 0; id < 4; ++id) {
        num[id] += __shfl_xor_sync(0xffffffffu, num[id], 1);
        num[id] += __shfl_xor_sync(0xffffffffu, num[id], 2);
        den[id] += __shfl_xor_sync(0xffffffffu, den[id], 1);
        den[id] += __shfl_xor_sync(0xffffffffu, den[id], 2);
    }
    if (cc == 0) {
#pragma unroll
        for (int mf = 0; mf < 2; ++mf)
#pragma unroll
            for (int hi = 0; hi < 2; ++hi) {
                int rl = wm * 32 + mf * 16 + g + hi * 8;
                red_n[rl][wn] = num[mf * 2 + hi];
                red_d[rl][wn] = den[mf * 2 + hi];
            }
    }

    // ---- Column-side reduce (over g: xor 4,8,16) ----
    if (offdiag) {
#pragma unroll
        for (int ci = 0; ci < 4; ++ci) {
            cn[ci] += __shfl_xor_sync(0xffffffffu, cn[ci], 4);
            cn[ci] += __shfl_xor_sync(0xffffffffu, cn[ci], 8);
            cn[ci] += __shfl_xor_sync(0xffffffffu, cn[ci], 16);
            cd[ci] += __shfl_xor_sync(0xffffffffu, cd[ci], 4);
            cd[ci] += __shfl_xor_sync(0xffffffffu, cd[ci], 8);
            cd[ci] += __shfl_xor_sync(0xffffffffu, cd[ci], 16);
        }
        if (g == 0) {
#pragma unroll
            for (int ci = 0; ci < 4; ++ci) {
                int nf = ci >> 1, e0 = ci & 1;
                int jl = wn * 16 + nf * 8 + 2 * cc + e0;
                colp_n[wm][jl] = cn[ci];
                colp_d[wm][jl] = cd[ci];
            }
        }
    }
    __syncthreads();

    if (tid < BT) {
        float rn = 0.f, rd = 0.f;
#pragma unroll
        for (int k = 0; k < 8; ++k) { rn += red_n[tid][k]; rd += red_d[tid][k]; }
        atomicAdd(&g_num[row0 + tid], rn);
        atomicAdd(&g_den[row0 + tid], rd);
        if (offdiag) {
            atomicAdd(&g_num[col0 + tid], colp_n[0][tid] + colp_n[1][tid]
                                        + colp_n[2][tid] + colp_n[3][tid]);
            atomicAdd(&g_den[col0 + tid], colp_d[0][tid] + colp_d[1][tid]
                                        + colp_d[2][tid] + colp_d[3][tid]);
        }
    }

    // --- Fused finalize: last CTA reduces everything, then resets state. ---
    __syncthreads();
    if (tid == 0) {
        __threadfence();
        unsigned prev = atomicAdd(&g_done, 1u);
        last_s = (prev == NTILES - 1) ? 1u : 0u;
    }
    __syncthreads();
    if (last_s) {
        __threadfence();
        double a = 0.0;
#pragma unroll
        for (int q = 0; q < N_PTS / NTHREADS; ++q) {
            int row = tid + q * NTHREADS;
            a += (double)g_num[row] * (double)g_den[row];
        }
        double bb = 0.0;
        if (tid < NUM_CLASSES) {
            double hh = (double)g_hist[tid];
            bb = hh * hh * ((double)N_PTS - hh);
        }
        s1[tid] = a; s2[tid] = bb;
        __syncthreads();
        for (int o = NTHREADS / 2; o; o >>= 1) {
            if (tid < o) { s1[tid] += s1[tid + o]; s2[tid] += s2[tid + o]; }
            __syncthreads();
        }
        if (tid == 0) out[0] = (float)(s1[0] / s2[0]);

        // Reset all accumulation state so the next graph replay starts clean.
#pragma unroll
        for (int q = 0; q < N_PTS / NTHREADS; ++q) {
            int row = tid + q * NTHREADS;
            g_num[row] = 0.f;
            g_den[row] = 0.f;
        }
        if (tid < NUM_CLASSES) g_hist[tid] = 0;
        if (tid == 0) g_done = 0u;
    }
}

// ---------------------------------------------------------------------------
extern "C" void kernel_launch(void* const* d_in, const int* in_sizes, int n_in,
                              void* d_out, int out_size) {
    const float* X   = (const float*)d_in[0];
    const int*   lab = (const int*)d_in[1];
    float*       out = (float*)d_out;

    prep_kernel<<<N_PTS / 8, 256>>>(X, lab);

    size_t smem = (size_t)2 * BT * SAB8;   // 69,632 B dynamic
    cudaFuncSetAttribute(triplet_main_kernel,
                         cudaFuncAttributeMaxDynamicSharedMemorySize, (int)smem);
    triplet_main_kernel<<<NTILES, NTHREADS, smem>>>(lab, out);
}

// round 17
// speedup vs baseline: 1.1111x; 1.1111x over previous
#include <cuda_runtime.h>
#include <cuda_bf16.h>
#include <cstdint>

#define N_PTS 8192
#define E_DIM 256
#define NUM_CLASSES 100
#define MARGIN 0.1f
#define EPS_F 1e-4f

#define BT 128                        // tile edge (rows and cols)
#define SAB8 272                      // padded row stride in bytes (LDSM conflict-free)
#define NRB (N_PTS / BT)              // 64 row blocks
#define NTILES (NRB * (NRB + 1) / 2)  // 2080 triangular tiles
#define NTHREADS 512

__device__ float g_sq[N_PTS];
__device__ int   g_hist[NUM_CLASSES];
__device__ float g_num[N_PTS];
__device__ float g_den[N_PTS];
__device__ unsigned g_done;
__device__ uint8_t g_x8[(size_t)N_PTS * E_DIM];   // e4m3 copy of X (2MB)

__device__ __forceinline__ void mma_fp8(float acc[4], const uint32_t a[4],
                                        const uint32_t b[2]) {
    asm volatile(
        "mma.sync.aligned.m16n8k32.row.col.f32.e4m3.e4m3.f32 "
        "{%0,%1,%2,%3}, {%4,%5,%6,%7}, {%8,%9}, {%0,%1,%2,%3};"
        : "+f"(acc[0]), "+f"(acc[1]), "+f"(acc[2]), "+f"(acc[3])
        : "r"(a[0]), "r"(a[1]), "r"(a[2]), "r"(a[3]), "r"(b[0]), "r"(b[1]));
}

__device__ __forceinline__ void ldsm_x4(uint32_t& r0, uint32_t& r1,
                                        uint32_t& r2, uint32_t& r3, uint32_t addr) {
    asm volatile("ldmatrix.sync.aligned.m8n8.x4.shared.b16 {%0,%1,%2,%3}, [%4];"
                 : "=r"(r0), "=r"(r1), "=r"(r2), "=r"(r3) : "r"(addr));
}

__device__ __forceinline__ uint32_t smem_u32(const void* p) {
    uint32_t a;
    asm("{ .reg .u64 t; cvta.to.shared.u64 t, %1; cvt.u32.u64 %0, t; }"
        : "=r"(a) : "l"(p));
    return a;
}

__device__ __forceinline__ uint16_t pack_e4m3x2(float lo, float hi) {
    uint16_t h;
    asm("cvt.rn.satfinite.e4m3x2.f32 %0, %1, %2;" : "=h"(h) : "f"(hi), "f"(lo));
    return h;
}

// ---------------------------------------------------------------------------
// Per-row squared norms (fp32 exact) + label histogram + e4m3 conversion.
// ---------------------------------------------------------------------------
__global__ void prep_kernel(const float* __restrict__ X, const int* __restrict__ lab) {
    int warp = (blockIdx.x * blockDim.x + threadIdx.x) >> 5;
    int lane = threadIdx.x & 31;
    if (warp >= N_PTS) return;
    const float4* row = (const float4*)(X + (size_t)warp * E_DIM);
    float4 v0 = row[2 * lane];
    float4 v1 = row[2 * lane + 1];
    float s = v0.x * v0.x + v0.y * v0.y + v0.z * v0.z + v0.w * v0.w
            + v1.x * v1.x + v1.y * v1.y + v1.z * v1.z + v1.w * v1.w;

    uint32_t w0 = (uint32_t)pack_e4m3x2(v0.x, v0.y)
                | ((uint32_t)pack_e4m3x2(v0.z, v0.w) << 16);
    uint32_t w1 = (uint32_t)pack_e4m3x2(v1.x, v1.y)
                | ((uint32_t)pack_e4m3x2(v1.z, v1.w) << 16);
    uint2 u; u.x = w0; u.y = w1;
    ((uint2*)(g_x8 + (size_t)warp * E_DIM))[lane] = u;

#pragma unroll
    for (int o = 16; o; o >>= 1) s += __shfl_xor_sync(0xffffffffu, s, o);
    if (lane == 0) {
        g_sq[warp] = s;
        atomicAdd(&g_hist[lab[warp]], 1);
    }
}

// ---------------------------------------------------------------------------
// Symmetric-Gram e4m3 m16n8k32 kernel with ldmatrix fragment loads.
// One CTA per triangular tile (I,J), J<=I. 512 threads = 16 warps,
// warp grid 4(m) x 4(n), warp tile 32x32.
// Off-diagonal tiles scatter BOTH row-side (I) and column-side (J) partials.
// Last CTA performs the final reduction AND resets state for the next replay.
// ---------------------------------------------------------------------------
__global__ void __launch_bounds__(NTHREADS, 1)
triplet_main_kernel(const int* __restrict__ lab, float* __restrict__ out) {
    extern __shared__ uint8_t smb[];
    uint8_t* As8 = smb;                  // BT x SAB8 (rows of I)
    uint8_t* Bs8 = smb + BT * SAB8;      // BT x SAB8 (rows of J = columns)

    __shared__ float sqb_s[BT];
    __shared__ int   lbb_s[BT];
    __shared__ float red_n[BT][4];
    __shared__ float red_d[BT][4];
    __shared__ float colp_n[4][BT];
    __shared__ float colp_d[4][BT];
    __shared__ unsigned last_s;
    __shared__ double s1[NTHREADS];
    __shared__ double s2[NTHREADS];

    const int tid  = threadIdx.x;
    const int w    = tid >> 5, lane = tid & 31;
    const int wm   = w >> 2,   wn   = w & 3;       // 4x4 warp grid
    const int g    = lane >> 2, cc  = lane & 3;

    // Triangular decode: blockIdx.x -> (I, J), J <= I.
    int b = blockIdx.x;
    int I = (int)((sqrtf(8.f * (float)b + 1.f) - 1.f) * 0.5f);
    while ((I + 1) * (I + 2) / 2 <= b) ++I;
    while (I * (I + 1) / 2 > b) --I;
    const int J = b - I * (I + 1) / 2;
    const bool offdiag = (I != J);

    const int row0 = I * BT;
    const int col0 = J * BT;
    const float DIAG_D = sqrtf(EPS_F);

    // Load A (I rows) and B (J rows): 2048 uint4 each, 4 per thread each.
#pragma unroll
    for (int q = 0; q < 4; ++q) {
        int idx = tid + q * NTHREADS;
        int r = idx >> 4, c16 = idx & 15;
        uint4 u = ((const uint4*)(g_x8 + (size_t)(row0 + r) * E_DIM))[c16];
        *(uint4*)(As8 + (size_t)r * SAB8 + c16 * 16) = u;
    }
#pragma unroll
    for (int q = 0; q < 4; ++q) {
        int idx = tid + q * NTHREADS;
        int r = idx >> 4, c16 = idx & 15;
        uint4 u = ((const uint4*)(g_x8 + (size_t)(col0 + r) * E_DIM))[c16];
        *(uint4*)(Bs8 + (size_t)r * SAB8 + c16 * 16) = u;
    }
    if (tid < BT) {
        sqb_s[tid] = g_sq[col0 + tid];
        lbb_s[tid] = lab[col0 + tid];
    }

    float sqa[4]; int la[4];
#pragma unroll
    for (int mf = 0; mf < 2; ++mf)
#pragma unroll
        for (int hi = 0; hi < 2; ++hi) {
            int r = row0 + wm * 32 + mf * 16 + g + hi * 8;
            sqa[mf * 2 + hi] = g_sq[r];
            la[mf * 2 + hi]  = lab[r];
        }
    __syncthreads();

    // ldmatrix per-lane base addresses. mi = lane>>3 (matrix id), ri = lane&7.
    // A x4 (per mf): m0=(rows+0,+0B) m1=(rows+8,+0B) m2=(rows+0,+16B) m3=(rows+8,+16B)
    //   -> regs a0..a3 as mma needs.
    // B x4 (per pair p of 2 nf): m0=(nf0,+0B) m1=(nf0,+16B) m2=(nf1,+0B) m3=(nf1,+16B)
    //   -> regs bb[nf0][0], bb[nf0][1], bb[nf1][0], bb[nf1][1].
    const int mi = lane >> 3, ri = lane & 7;
    const uint32_t as_b = smem_u32(As8);
    const uint32_t bs_b = smem_u32(Bs8);
    uint32_t aAddr[2], bAddr[2];
#pragma unroll
    for (int mf = 0; mf < 2; ++mf)
        aAddr[mf] = as_b + (uint32_t)(wm * 32 + mf * 16 + ((mi & 1) << 3) + ri) * SAB8
                  + ((mi >> 1) << 4);
#pragma unroll
    for (int p = 0; p < 2; ++p)
        bAddr[p] = bs_b + (uint32_t)(wn * 32 + p * 16 + ((mi >> 1) << 3) + ri) * SAB8
                 + ((mi & 1) << 4);

    float acc[2][4][4];
#pragma unroll
    for (int mf = 0; mf < 2; ++mf)
#pragma unroll
        for (int nf = 0; nf < 4; ++nf)
#pragma unroll
            for (int e = 0; e < 4; ++e) acc[mf][nf][e] = 0.f;

#pragma unroll
    for (int ks = 0; ks < E_DIM / 32; ++ks) {
        const uint32_t kc = ks * 32;
        uint32_t a[2][4], bb[4][2];
        ldsm_x4(a[0][0], a[0][1], a[0][2], a[0][3], aAddr[0] + kc);
        ldsm_x4(a[1][0], a[1][1], a[1][2], a[1][3], aAddr[1] + kc);
        ldsm_x4(bb[0][0], bb[0][1], bb[1][0], bb[1][1], bAddr[0] + kc);
        ldsm_x4(bb[2][0], bb[2][1], bb[3][0], bb[3][1], bAddr[1] + kc);
#pragma unroll
        for (int mf = 0; mf < 2; ++mf)
#pragma unroll
            for (int nf = 0; nf < 4; ++nf)
                mma_fp8(acc[mf][nf], a[mf], bb[nf]);
    }

    // Epilogue: one rsqrt per element; value feeds row (I) and column (J) sums.
    float num[4] = {0.f, 0.f, 0.f, 0.f};
    float den[4] = {0.f, 0.f, 0.f, 0.f};
    float cn[8]  = {0.f, 0.f, 0.f, 0.f, 0.f, 0.f, 0.f, 0.f};
    float cd[8]  = {0.f, 0.f, 0.f, 0.f, 0.f, 0.f, 0.f, 0.f};

    float sj[4][2]; int lj[4][2];
#pragma unroll
    for (int nf = 0; nf < 4; ++nf)
#pragma unroll
        for (int e0 = 0; e0 < 2; ++e0) {
            int jl = wn * 32 + nf * 8 + 2 * cc + e0;
            sj[nf][e0] = sqb_s[jl];
            lj[nf][e0] = lbb_s[jl];
        }

#pragma unroll
    for (int mf = 0; mf < 2; ++mf)
#pragma unroll
        for (int nf = 0; nf < 4; ++nf)
#pragma unroll
            for (int e = 0; e < 4; ++e) {
                int hi = e >> 1, e0 = e & 1;
                int id = mf * 2 + hi;
                int ci = nf * 2 + e0;
                float v = fmaxf(sqa[id] + sj[nf][e0] - 2.f * acc[mf][nf][e], EPS_F);
                float r;
                asm("rsqrt.approx.f32 %0, %1;" : "=f"(r) : "f"(v));
                if (la[id] == lj[nf][e0]) {
                    float c;
                    if (offdiag) {
                        c = v * r;
                    } else {
                        int il = wm * 32 + mf * 16 + g + hi * 8;
                        int jl = wn * 32 + nf * 8 + 2 * cc + e0;
                        c = (il == jl) ? DIAG_D : v * r;
                    }
                    num[id] += c;
                    cn[ci]  += c;
                } else {
                    float t = MARGIN * r;
                    float u = 1.f - t;
                    float c = r * fmaf(t * t, u, u);   // 1/(d+m) ~ r(1-t)(1+t^2)
                    den[id] += c;
                    cd[ci]  += c;
                }
            }

    // ---- Row-side reduce (over cc: xor 1,2 stays within quad) ----
#pragma unroll
    for (int id = 0; id < 4; ++id) {
        num[id] += __shfl_xor_sync(0xffffffffu, num[id], 1);
        num[id] += __shfl_xor_sync(0xffffffffu, num[id], 2);
        den[id] += __shfl_xor_sync(0xffffffffu, den[id], 1);
        den[id] += __shfl_xor_sync(0xffffffffu, den[id], 2);
    }
    if (cc == 0) {
#pragma unroll
        for (int mf = 0; mf < 2; ++mf)
#pragma unroll
            for (int hi = 0; hi < 2; ++hi) {
                int rl = wm * 32 + mf * 16 + g + hi * 8;
                red_n[rl][wn] = num[mf * 2 + hi];
                red_d[rl][wn] = den[mf * 2 + hi];
            }
    }

    // ---- Column-side reduce (over g: xor 4,8,16) ----
    if (offdiag) {
#pragma unroll
        for (int ci = 0; ci < 8; ++ci) {
            cn[ci] += __shfl_xor_sync(0xffffffffu, cn[ci], 4);
            cn[ci] += __shfl_xor_sync(0xffffffffu, cn[ci], 8);
            cn[ci] += __shfl_xor_sync(0xffffffffu, cn[ci], 16);
            cd[ci] += __shfl_xor_sync(0xffffffffu, cd[ci], 4);
            cd[ci] += __shfl_xor_sync(0xffffffffu, cd[ci], 8);
            cd[ci] += __shfl_xor_sync(0xffffffffu, cd[ci], 16);
        }
        if (g == 0) {
#pragma unroll
            for (int ci = 0; ci < 8; ++ci) {
                int nf = ci >> 1, e0 = ci & 1;
                int jl = wn * 32 + nf * 8 + 2 * cc + e0;
                colp_n[wm][jl] = cn[ci];
                colp_d[wm][jl] = cd[ci];
            }
        }
    }
    __syncthreads();

    if (tid < BT) {
        atomicAdd(&g_num[row0 + tid], red_n[tid][0] + red_n[tid][1]
                                    + red_n[tid][2] + red_n[tid][3]);
        atomicAdd(&g_den[row0 + tid], red_d[tid][0] + red_d[tid][1]
                                    + red_d[tid][2] + red_d[tid][3]);
        if (offdiag) {
            atomicAdd(&g_num[col0 + tid], colp_n[0][tid] + colp_n[1][tid]
                                        + colp_n[2][tid] + colp_n[3][tid]);
            atomicAdd(&g_den[col0 + tid], colp_d[0][tid] + colp_d[1][tid]
                                        + colp_d[2][tid] + colp_d[3][tid]);
        }
    }

    // --- Fused finalize: last CTA reduces everything, then resets state. ---
    __syncthreads();
    if (tid == 0) {
        __threadfence();
        unsigned prev = atomicAdd(&g_done, 1u);
        last_s = (prev == NTILES - 1) ? 1u : 0u;
    }
    __syncthreads();
    if (last_s) {
        __threadfence();
        double a = 0.0;
#pragma unroll
        for (int q = 0; q < N_PTS / NTHREADS; ++q) {
            int row = tid + q * NTHREADS;
            a += (double)g_num[row] * (double)g_den[row];
        }
        double bb2 = 0.0;
        if (tid < NUM_CLASSES) {
            double hh = (double)g_hist[tid];
            bb2 = hh * hh * ((double)N_PTS - hh);
        }
        s1[tid] = a; s2[tid] = bb2;
        __syncthreads();
        for (int o = NTHREADS / 2; o; o >>= 1) {
            if (tid < o) { s1[tid] += s1[tid + o]; s2[tid] += s2[tid + o]; }
            __syncthreads();
        }
        if (tid == 0) out[0] = (float)(s1[0] / s2[0]);

        // Reset all accumulation state so the next graph replay starts clean.
#pragma unroll
        for (int q = 0; q < N_PTS / NTHREADS; ++q) {
            int row = tid + q * NTHREADS;
            g_num[row] = 0.f;
            g_den[row] = 0.f;
        }
        if (tid < NUM_CLASSES) g_hist[tid] = 0;
        if (tid == 0) g_done = 0u;
    }
}

// ---------------------------------------------------------------------------
extern "C" void kernel_launch(void* const* d_in, const int* in_sizes, int n_in,
                              void* d_out, int out_size) {
    const float* X   = (const float*)d_in[0];
    const int*   lab = (const int*)d_in[1];
    float*       out = (float*)d_out;

    prep_kernel<<<N_PTS / 8, 256>>>(X, lab);

    size_t smem = (size_t)2 * BT * SAB8;   // 69,632 B dynamic
    cudaFuncSetAttribute(triplet_main_kernel,
                         cudaFuncAttributeMaxDynamicSharedMemorySize, (int)smem);
    triplet_main_kernel<<<NTILES, NTHREADS, smem>>>(lab, out);
}